// round 1
// baseline (speedup 1.0000x reference)
#include <cuda_runtime.h>
#include <math.h>

#define Bn 32
#define Tn 512
#define Hn 2048
#define Kn 128

// Scratch (no allocations allowed)
__device__ float g_logits[Bn * Tn * Kn];   // 8 MB
__device__ float g_llh[Bn];

// ---------------------------------------------------------------------------
// GEMM: logits[m][n] = sum_h hiddens[m][h] * W[h][n] + b[n]
// M = B*T = 16384, N = K = 128, reduction = H = 2048. fp32 SIMT, tiled.
// BM=64, BN=128, BK=16, 256 threads, 8x4 per-thread tile.
// ---------------------------------------------------------------------------
__global__ __launch_bounds__(256) void gemm_kernel(
    const float* __restrict__ hid, const float* __restrict__ W,
    const float* __restrict__ bias)
{
    __shared__ float As[16][64];    // transposed: As[k][m]
    __shared__ float Bs[16][128];

    const int tid = threadIdx.x;
    const int m0  = blockIdx.x * 64;
    const int ty  = tid >> 5;       // 0..7 row group
    const int tx  = tid & 31;       // 0..31 col group

    float acc[8][4];
#pragma unroll
    for (int i = 0; i < 8; i++)
#pragma unroll
        for (int jj = 0; jj < 4; jj++) acc[i][jj] = 0.f;

    const int arow = tid >> 2;            // 0..63
    const int ac4  = (tid & 3) * 4;       // 0,4,8,12

    for (int k0 = 0; k0 < Hn; k0 += 16) {
        // Load A tile (64x16) transposed into As
        float4 a4 = *(const float4*)(hid + (size_t)(m0 + arow) * Hn + k0 + ac4);
        As[ac4 + 0][arow] = a4.x;
        As[ac4 + 1][arow] = a4.y;
        As[ac4 + 2][arow] = a4.z;
        As[ac4 + 3][arow] = a4.w;
        // Load B tile (16x128): two float4 per thread
        {
            int idx = tid;
            int r = idx >> 5, c = (idx & 31) * 4;
            *(float4*)(&Bs[r][c]) = *(const float4*)(W + (size_t)(k0 + r) * Kn + c);
            idx = tid + 256;
            r = idx >> 5; c = (idx & 31) * 4;
            *(float4*)(&Bs[r][c]) = *(const float4*)(W + (size_t)(k0 + r) * Kn + c);
        }
        __syncthreads();

#pragma unroll
        for (int k = 0; k < 16; k++) {
            float4 b4 = *(const float4*)(&Bs[k][tx * 4]);
            float a[8];
#pragma unroll
            for (int i = 0; i < 8; i++) a[i] = As[k][ty * 8 + i];
#pragma unroll
            for (int i = 0; i < 8; i++) {
                acc[i][0] += a[i] * b4.x;
                acc[i][1] += a[i] * b4.y;
                acc[i][2] += a[i] * b4.z;
                acc[i][3] += a[i] * b4.w;
            }
        }
        __syncthreads();
    }

    const int n0 = tx * 4;
    float4 bb = *(const float4*)(bias + n0);
#pragma unroll
    for (int i = 0; i < 8; i++) {
        int row = m0 + ty * 8 + i;
        float4 o;
        o.x = acc[i][0] + bb.x;
        o.y = acc[i][1] + bb.y;
        o.z = acc[i][2] + bb.z;
        o.w = acc[i][3] + bb.w;
        *(float4*)(g_logits + (size_t)row * Kn + n0) = o;
    }
}

// ---------------------------------------------------------------------------
// CRF recurrences. 64 blocks x 256 threads.
// blocks [0,32): forward logsumexp + path score -> g_llh[b]
// blocks [32,64): viterbi decode -> out[b*T .. ] (tags as float)
// Thread mapping: j = tid>>1 (tag column), h = tid&1 (row half).
// ---------------------------------------------------------------------------
__global__ __launch_bounds__(256) void crf_kernel(
    const int* __restrict__ mask, const int* __restrict__ labels,
    const float* __restrict__ startT, const float* __restrict__ endT,
    const float* __restrict__ trans, float* __restrict__ out)
{
    extern __shared__ char smem[];
    float* sh_s  = (float*)smem;                 // 128 floats
    float* shred = (float*)(smem + 512);         // reduce scratch (floats)
    int*   shredi = (int*)(smem + 512 + 256);    // reduce scratch (ints)
    unsigned char* bp = (unsigned char*)(smem + 1024); // 511*128 bytes

    const int tid = threadIdx.x;
    const int j = tid >> 1, h = tid & 1;
    const unsigned FULL = 0xFFFFFFFFu;
    const int bidx = blockIdx.x;

    if (bidx < Bn) {
        // ================= FORWARD =================
        const int b = bidx;
        float Eh[64];
#pragma unroll
        for (int i = 0; i < 64; i++)
            Eh[i] = expf(trans[(h * 64 + i) * Kn + j]);

        const float* lg = g_logits + (size_t)b * Tn * Kn;
        float alpha = startT[j] + lg[j];
        float e_next = lg[Kn + j];

        for (int t = 1; t < Tn; t++) {
            float emit = e_next;
            if (t + 1 < Tn) e_next = lg[(size_t)(t + 1) * Kn + j];
            int mt = mask[b * Tn + t];

            // block max of alpha
            float wm = alpha;
#pragma unroll
            for (int o = 16; o; o >>= 1)
                wm = fmaxf(wm, __shfl_xor_sync(FULL, wm, o));
            if ((tid & 31) == 0) shred[tid >> 5] = wm;
            __syncthreads();                       // S1
            float m = shred[0];
#pragma unroll
            for (int w = 1; w < 8; w++) m = fmaxf(m, shred[w]);

            float p = expf(alpha - m);
            if (h == 0) sh_s[j] = p;
            __syncthreads();                       // S2

            float s = 0.f;
            const float4* p4 = (const float4*)(sh_s + h * 64);
#pragma unroll
            for (int i4 = 0; i4 < 16; i4++) {
                float4 v = p4[i4];
                s += v.x * Eh[i4 * 4 + 0];
                s += v.y * Eh[i4 * 4 + 1];
                s += v.z * Eh[i4 * 4 + 2];
                s += v.w * Eh[i4 * 4 + 3];
            }
            s += __shfl_xor_sync(FULL, s, 1);
            float nxt = m + logf(s) + emit;
            alpha = (mt > 0) ? nxt : alpha;
        }

        // logZ = logsumexp_j(alpha_j + end_j)
        __syncthreads();
        float v = alpha + endT[j];
        float wm = v;
#pragma unroll
        for (int o = 16; o; o >>= 1)
            wm = fmaxf(wm, __shfl_xor_sync(FULL, wm, o));
        if ((tid & 31) == 0) shred[tid >> 5] = wm;
        __syncthreads();
        float m = shred[0];
#pragma unroll
        for (int w = 1; w < 8; w++) m = fmaxf(m, shred[w]);
        __syncthreads();
        float pc = (h == 0) ? expf(v - m) : 0.f;
#pragma unroll
        for (int o = 16; o; o >>= 1)
            pc += __shfl_xor_sync(FULL, pc, o);
        if ((tid & 31) == 0) shred[tid >> 5] = pc;
        __syncthreads();
        float Z = 0.f;
#pragma unroll
        for (int w = 0; w < 8; w++) Z += shred[w];
        float logZ = m + logf(Z);
        __syncthreads();

        // path score
        float sc = 0.f;
        int msum = 0;
        for (int t = tid; t < Tn; t += 256) {
            msum += mask[b * Tn + t];
            if (t >= 1) {
                int cur  = labels[b * Tn + t];
                int prev = labels[b * Tn + t - 1];
                float mf = (float)mask[b * Tn + t];
                sc += (trans[prev * Kn + cur] + lg[(size_t)t * Kn + cur]) * mf;
            }
        }
#pragma unroll
        for (int o = 16; o; o >>= 1) {
            sc   += __shfl_xor_sync(FULL, sc, o);
            msum += __shfl_xor_sync(FULL, msum, o);
        }
        if ((tid & 31) == 0) { shred[tid >> 5] = sc; shredi[tid >> 5] = msum; }
        __syncthreads();
        if (tid == 0) {
            float S = 0.f; int M = 0;
#pragma unroll
            for (int w = 0; w < 8; w++) { S += shred[w]; M += shredi[w]; }
            int l0 = labels[b * Tn];
            S += startT[l0] + lg[l0];
            int last = labels[b * Tn + (M - 1)];
            S += endT[last];
            g_llh[b] = S - logZ;
        }
    } else {
        // ================= VITERBI =================
        const int b = bidx - Bn;
        float Th[64];
#pragma unroll
        for (int i = 0; i < 64; i++)
            Th[i] = trans[(h * 64 + i) * Kn + j];

        const float* lg = g_logits + (size_t)b * Tn * Kn;
        float sj = startT[j] + lg[j];
        if (h == 0) sh_s[j] = sj;
        float e_next = lg[Kn + j];
        __syncthreads();

        for (int t = 1; t < Tn; t++) {
            float emit = e_next;
            if (t + 1 < Tn) e_next = lg[(size_t)(t + 1) * Kn + j];
            int mt = mask[b * Tn + t];

            float best = -3.4e38f;
            int arg = 0;
            const float4* s4 = (const float4*)(sh_s + h * 64);
#pragma unroll
            for (int i4 = 0; i4 < 16; i4++) {
                float4 v = s4[i4];
                float c0 = v.x + Th[i4 * 4 + 0];
                float c1 = v.y + Th[i4 * 4 + 1];
                float c2 = v.z + Th[i4 * 4 + 2];
                float c3 = v.w + Th[i4 * 4 + 3];
                if (c0 > best) { best = c0; arg = i4 * 4 + 0; }
                if (c1 > best) { best = c1; arg = i4 * 4 + 1; }
                if (c2 > best) { best = c2; arg = i4 * 4 + 2; }
                if (c3 > best) { best = c3; arg = i4 * 4 + 3; }
            }
            int ai = h * 64 + arg;
            float ob = __shfl_xor_sync(FULL, best, 1);
            int   oi = __shfl_xor_sync(FULL, ai, 1);
            // first-index-on-tie: lower-index candidate is the h==0 one
            float lb = (h == 0) ? best : ob;
            int   li = (h == 0) ? ai   : oi;
            float hb = (h == 0) ? ob   : best;
            int   hi = (h == 0) ? oi   : ai;
            float fb; int fa;
            if (hb > lb) { fb = hb; fa = hi; } else { fb = lb; fa = li; }

            float ns; int bpv;
            if (mt > 0) { ns = fb + emit; bpv = fa; }
            else        { ns = sj;        bpv = j;  }
            sj = ns;
            __syncthreads();                       // S1 (reads done)
            if (h == 0) {
                sh_s[j] = sj;
                bp[(size_t)(t - 1) * Kn + j] = (unsigned char)bpv;
            }
            __syncthreads();                       // S2 (writes visible)
        }

        if (h == 0) sh_s[j] = sj + endT[j];
        __syncthreads();
        if (tid == 0) {
            float bbest = sh_s[0];
            int btag = 0;
            for (int q = 1; q < Kn; q++) {
                float vv = sh_s[q];
                if (vv > bbest) { bbest = vv; btag = q; }
            }
            int tag = btag;
            out[b * Tn + (Tn - 1)] = (float)tag;
            for (int t = Tn - 2; t >= 0; t--) {
                tag = bp[(size_t)t * Kn + tag];
                out[b * Tn + t] = (float)tag;
            }
        }
    }
}

// ---------------------------------------------------------------------------
// loss = -mean(llh)
// ---------------------------------------------------------------------------
__global__ void loss_kernel(float* __restrict__ out)
{
    const unsigned FULL = 0xFFFFFFFFu;
    float v = (threadIdx.x < Bn) ? g_llh[threadIdx.x] : 0.f;
#pragma unroll
    for (int o = 16; o; o >>= 1) v += __shfl_xor_sync(FULL, v, o);
    if (threadIdx.x == 0) out[Bn * Tn] = -(v / (float)Bn);
}

extern "C" void kernel_launch(void* const* d_in, const int* in_sizes, int n_in,
                              void* d_out, int out_size)
{
    const float* hiddens = (const float*)d_in[0];
    const int*   mask    = (const int*)d_in[1];
    const int*   labels  = (const int*)d_in[2];
    const float* W       = (const float*)d_in[3];
    const float* bias    = (const float*)d_in[4];
    const float* startT  = (const float*)d_in[5];
    const float* endT    = (const float*)d_in[6];
    const float* trans   = (const float*)d_in[7];
    float* out = (float*)d_out;

    gemm_kernel<<<(Bn * Tn) / 64, 256>>>(hiddens, W, bias);

    size_t smem = 1024 + (size_t)(Tn - 1) * Kn;  // 1024 + 65408 = 66432 B
    cudaFuncSetAttribute(crf_kernel, cudaFuncAttributeMaxDynamicSharedMemorySize,
                         (int)smem);
    crf_kernel<<<2 * Bn, 256, smem>>>(mask, labels, startT, endT, trans, out);

    loss_kernel<<<1, 32>>>(out);
}